// round 15
// baseline (speedup 1.0000x reference)
#include <cuda_runtime.h>
#include <cuda_fp16.h>
#include <math.h>
#include <stdint.h>

#define NUM_INITS   64
#define BATCH_N     128
#define TOTAL_P     18378
#define OFF_W1      0
#define OFF_B1      400
#define OFF_W2      416
#define OFF_B2      13216
#define OFF_WD      13248
#define OFF_BD      18368

// dynamic smem byte offsets
#define O_AH    0           // a1 hi: half[2*12*12*24] = 13824 B
#define O_AL    13824       // a1 lo
#define O_BH    27648       // w2 hi: half[25*32*24] = 38400 B  (ci padded 16->24)
#define O_BL    66048       // w2 lo
#define O_SA2   104448      // float[2][512]
#define O_SW1   108544      // float[400]
#define O_SB1   110144      // float[16]
#define O_SB2   110208      // float[32]
#define O_SDOT  110336      // float[2][16]
#define SMEM_BYTES 110464

// A layout (halves): idx = ((img*12 + y)*12 + x)*24 + ci   (ci stride 24 -> conflict-free frags)
#define A_X  24
#define A_Y  288            // 12 * 24
#define A_I  3456           // 12 * 288
// B layout (halves): idx = (tap*32 + c2)*24 + ci
#define B_T  768            // 32 * 24

static __device__ __forceinline__ void mma_f16(float* d, const uint32_t* a, const uint32_t* b) {
    asm volatile(
        "mma.sync.aligned.m16n8k16.row.col.f32.f16.f16.f32 "
        "{%0,%1,%2,%3}, {%4,%5,%6,%7}, {%8,%9}, {%0,%1,%2,%3};"
        : "+f"(d[0]), "+f"(d[1]), "+f"(d[2]), "+f"(d[3])
        : "r"(a[0]), "r"(a[1]), "r"(a[2]), "r"(a[3]), "r"(b[0]), "r"(b[1]));
}

__global__ __launch_bounds__(256, 2)
void ensemble_lenet_mma(const float* __restrict__ params,
                        const float* __restrict__ batch,
                        float* __restrict__ out)
{
    extern __shared__ __align__(16) char smem[];
    half*  AH   = (half*)(smem + O_AH);
    half*  AL   = (half*)(smem + O_AL);
    half*  BH   = (half*)(smem + O_BH);
    half*  BL   = (half*)(smem + O_BL);
    float* sa2  = (float*)(smem + O_SA2);
    float* sw1  = (float*)(smem + O_SW1);
    float* sb1  = (float*)(smem + O_SB1);
    float* sb2  = (float*)(smem + O_SB2);
    float* sdot = (float*)(smem + O_SDOT);

    const int blk   = blockIdx.x;
    const int init  = blk >> 6;
    const int npair = blk & 63;
    const int t     = threadIdx.x;
    const int img   = t >> 7;
    const int tl    = t & 127;

    const float* __restrict__ P = params + init * TOTAL_P;

    // ---------- stage 2 images (into BH region, pre-B) + conv1 params ----------
    {
        float* simg = (float*)(smem + O_BH);
        const float* ib = batch + (npair * 2) * 784;
        for (int idx = t; idx < 1568; idx += 256) simg[idx] = ib[idx];
        for (int idx = t; idx < 400;  idx += 256) sw1[idx] = P[idx];
        if (t < 16) sb1[t] = P[OFF_B1 + t];
        if (t < 32) sb2[t] = P[OFF_B2 + t];
    }
    __syncthreads();

    // ---------- conv1 + relu + pool -> AH/AL (fp16 hi/lo split) ----------
    {
        const int co = (tl >> 3) & 15;
        const int l8 = tl & 7;
        float w1r[25];
        #pragma unroll
        for (int q = 0; q < 25; q++) w1r[q] = sw1[co * 25 + q];
        const float b1 = sb1[co];
        const float* imgp = (const float*)(smem + O_BH) + img * 784;

        #pragma unroll 2
        for (int k = 0; k < 18; k++) {
            const int idx = l8 + (k << 3);       // 0..143
            const int py = idx / 12;
            const int px = idx - py * 12;
            const int iy = py * 2, ix = px * 2;

            float a00 = b1, a01 = b1, a10 = b1, a11 = b1;
            #pragma unroll
            for (int r = 0; r < 6; r++) {
                const float2* rp = (const float2*)(imgp + (iy + r) * 28 + ix);
                const float2 v0 = rp[0], v1 = rp[1], v2 = rp[2];
                float row[6];
                row[0]=v0.x; row[1]=v0.y; row[2]=v1.x; row[3]=v1.y; row[4]=v2.x; row[5]=v2.y;
                if (r < 5) {
                    #pragma unroll
                    for (int dx = 0; dx < 5; dx++) {
                        const float w = w1r[r * 5 + dx];
                        a00 = fmaf(row[dx],     w, a00);
                        a01 = fmaf(row[dx + 1], w, a01);
                    }
                }
                if (r >= 1) {
                    #pragma unroll
                    for (int dx = 0; dx < 5; dx++) {
                        const float w = w1r[(r - 1) * 5 + dx];
                        a10 = fmaf(row[dx],     w, a10);
                        a11 = fmaf(row[dx + 1], w, a11);
                    }
                }
            }
            const float v = fmaxf(fmaxf(fmaxf(a00, a01), fmaxf(a10, a11)), 0.0f);
            const half vh = __float2half_rn(v);
            const half vl = __float2half_rn(v - __half2float(vh));
            const int ai = img * A_I + py * A_Y + px * A_X + co;
            AH[ai] = vh;
            AL[ai] = vl;
        }
    }
    __syncthreads();

    // ---------- stage conv2 weights, fp16 hi/lo split: BH/BL[tap][c2][ci] ----------
    for (int e = t; e < 12800; e += 256) {
        const int c2  = e / 400;
        const int r   = e - c2 * 400;
        const int ci  = r / 25;
        const int tap = r - ci * 25;
        const float v = P[OFF_W2 + e];
        const half vh = __float2half_rn(v);
        const half vl = __float2half_rn(v - __half2float(vh));
        const int bi = (tap * 32 + c2) * 24 + ci;
        BH[bi] = vh;
        BL[bi] = vl;
    }
    __syncthreads();

    // ---------- conv2 via mma.sync m16n8k16 fp16, 3-pass hi/lo ----------
    // warp w: m-block mb = w&3 (2 m-tiles of 16 rows), n-block nb = w>>2 (2 n-tiles of 8).
    // m = img*64 + py*8 + px; m-tile tau: img = tau>>2, py base = (tau&3)*2.
    const int lane = t & 31;
    const int w    = t >> 5;
    const int g    = lane >> 2;
    const int tq   = lane & 3;
    const int mb   = w & 3;
    const int nb   = w >> 2;
    const int imw  = mb >> 1;

    float acc[2][2][4];
    #pragma unroll
    for (int i = 0; i < 2; i++)
        #pragma unroll
        for (int j = 0; j < 2; j++)
            #pragma unroll
            for (int q = 0; q < 4; q++) acc[i][j][q] = 0.0f;

    #pragma unroll
    for (int dy = 0; dy < 5; dy++) {
        #pragma unroll
        for (int dx = 0; dx < 5; dx++) {
            const int tap = dy * 5 + dx;

            uint32_t ah[2][4], al[2][4];
            #pragma unroll
            for (int mt = 0; mt < 2; mt++) {
                const int tau = 2 * mb + mt;
                const int pyb = (tau & 3) * 2;
                const int b0 = imw * A_I + (pyb + dy) * A_Y + (g + dx) * A_X + 2 * tq;
                const int b1 = b0 + A_Y;          // py+1 (rows 8..15)
                ah[mt][0] = *(const uint32_t*)(AH + b0);
                ah[mt][1] = *(const uint32_t*)(AH + b1);
                ah[mt][2] = *(const uint32_t*)(AH + b0 + 8);
                ah[mt][3] = *(const uint32_t*)(AH + b1 + 8);
                al[mt][0] = *(const uint32_t*)(AL + b0);
                al[mt][1] = *(const uint32_t*)(AL + b1);
                al[mt][2] = *(const uint32_t*)(AL + b0 + 8);
                al[mt][3] = *(const uint32_t*)(AL + b1 + 8);
            }
            uint32_t bh[2][2], bl[2][2];
            #pragma unroll
            for (int nt = 0; nt < 2; nt++) {
                const int c2 = nb * 16 + nt * 8 + g;
                const int bb = tap * B_T + c2 * 24 + 2 * tq;
                bh[nt][0] = *(const uint32_t*)(BH + bb);
                bh[nt][1] = *(const uint32_t*)(BH + bb + 8);
                bl[nt][0] = *(const uint32_t*)(BL + bb);
                bl[nt][1] = *(const uint32_t*)(BL + bb + 8);
            }
            #pragma unroll
            for (int mt = 0; mt < 2; mt++)
                #pragma unroll
                for (int nt = 0; nt < 2; nt++) {
                    mma_f16(acc[mt][nt], ah[mt], bh[nt]);
                    mma_f16(acc[mt][nt], ah[mt], bl[nt]);
                    mma_f16(acc[mt][nt], al[mt], bh[nt]);
                }
        }
    }

    // ---------- epilogue: bias + relu + 2x2 pool -> sa2[img][pos16*32 + c2] ----------
    #pragma unroll
    for (int mt = 0; mt < 2; mt++) {
        const int tau = 2 * mb + mt;
        const int ppy = tau & 3;
        #pragma unroll
        for (int nt = 0; nt < 2; nt++) {
            #pragma unroll
            for (int cp = 0; cp < 2; cp++) {
                // d[cp] row g (py base), d[cp+2] row g+8 (py base+1); cols 2tq+cp
                float v = fmaxf(acc[mt][nt][cp], acc[mt][nt][cp + 2]);
                v = fmaxf(v, __shfl_xor_sync(0xFFFFFFFFu, v, 4));   // px pair (g, g^1)
                if ((g & 1) == 0) {
                    const int c2  = nb * 16 + nt * 8 + 2 * tq + cp;
                    const int ppx = g >> 1;
                    sa2[imw * 512 + (ppy * 4 + ppx) * 32 + c2] =
                        fmaxf(v + sb2[c2], 0.0f);
                }
            }
        }
    }
    __syncthreads();

    // ---------- dense 512 -> 10 (warp-uniform, from R12-passing code) ----------
    {
        const int o  = tl >> 3;
        const int oc = (o < 10) ? o : 9;
        const int l  = tl & 7;
        const float2* wr2 = (const float2*)(P + OFF_WD + oc * 512 + l * 64);
        const float* a2 = sa2 + img * 512;
        float partial = 0.0f;
        #pragma unroll
        for (int i2 = 0; i2 < 32; i2++) {
            const float2 wv = wr2[i2];
            const int f0 = l * 64 + i2 * 2;
            partial = fmaf(wv.x, a2[((f0    ) & 15) * 32 + ((f0    ) >> 4)], partial);
            partial = fmaf(wv.y, a2[((f0 + 1) & 15) * 32 + ((f0 + 1) >> 4)], partial);
        }
        #pragma unroll
        for (int off = 4; off; off >>= 1)
            partial += __shfl_down_sync(0xFFFFFFFFu, partial, off, 8);
        if (l == 0 && o < 10) sdot[img * 16 + o] = partial + P[OFF_BD + o];
    }
    __syncthreads();

    // ---------- log_softmax over 10, write out ----------
    if (t < 64) {
        const int im = t >> 5;
        const int lane2 = t & 31;
        const float v = (lane2 < 10) ? sdot[im * 16 + lane2] : -INFINITY;
        float mx = v;
        #pragma unroll
        for (int off = 16; off; off >>= 1)
            mx = fmaxf(mx, __shfl_xor_sync(0xFFFFFFFFu, mx, off));
        const float e = (lane2 < 10) ? __expf(v - mx) : 0.0f;
        float s = e;
        #pragma unroll
        for (int off = 16; off; off >>= 1)
            s += __shfl_xor_sync(0xFFFFFFFFu, s, off);
        if (lane2 < 10) {
            const int n = npair * 2 + im;
            out[(init * BATCH_N + n) * 10 + lane2] = v - mx - __logf(s);
        }
    }
}

extern "C" void kernel_launch(void* const* d_in, const int* in_sizes, int n_in,
                              void* d_out, int out_size)
{
    const float* params = (const float*)d_in[0];
    const float* batch  = (const float*)d_in[1];
    if (n_in >= 2 && in_sizes[0] != NUM_INITS * TOTAL_P) {
        params = (const float*)d_in[1];
        batch  = (const float*)d_in[0];
    }
    float* out = (float*)d_out;
    cudaFuncSetAttribute(ensemble_lenet_mma,
                         cudaFuncAttributeMaxDynamicSharedMemorySize, SMEM_BYTES);
    ensemble_lenet_mma<<<NUM_INITS * (BATCH_N / 2), 256, SMEM_BYTES>>>(params, batch, out);
}

// round 16
// speedup vs baseline: 1.0634x; 1.0634x over previous
#include <cuda_runtime.h>
#include <cuda_fp16.h>
#include <math.h>
#include <stdint.h>

#define NUM_INITS   64
#define BATCH_N     128
#define TOTAL_P     18378
#define OFF_W1      0
#define OFF_B1      400
#define OFF_W2      416
#define OFF_B2      13216
#define OFF_WD      13248
#define OFF_BD      18368

// dynamic smem byte offsets
#define O_AH    0           // a1 fp16: half[2*12*12*24] = 13824 B
#define O_BH    13824       // w2 hi: half[25*32*24] = 38400 B (ci padded 16->24)
#define O_BL    52224       // w2 lo: 38400 B
#define O_SA2   90624       // float[2][512] = 4096
#define O_SW1   94720       // float[400] = 1600
#define O_SB1   96320       // float[16]
#define O_SB2   96384       // float[32]
#define O_SDOT  96512       // float[2][16]
#define SMEM_BYTES 96640

// A layout: idx = ((img*12 + y)*12 + x)*24 + ci  (halves; stride 24 -> LDSM conflict-free)
#define A_X  24
#define A_Y  288            // 12 * 24
#define A_I  3456           // 12 * 288
// B layout: idx = (tap*32 + c2)*24 + ci
#define B_T  768            // 32 * 24

static __device__ __forceinline__ uint32_t smem_u32(const void* p) {
    uint32_t a;
    asm("{ .reg .u64 t; cvta.to.shared.u64 t, %1; cvt.u32.u64 %0, t; }" : "=r"(a) : "l"(p));
    return a;
}
static __device__ __forceinline__ void ldsm_x4(uint32_t* r, uint32_t a) {
    asm volatile("ldmatrix.sync.aligned.m8n8.x4.shared.b16 {%0,%1,%2,%3}, [%4];"
                 : "=r"(r[0]), "=r"(r[1]), "=r"(r[2]), "=r"(r[3]) : "r"(a));
}
static __device__ __forceinline__ void ldsm_x2(uint32_t* r, uint32_t a) {
    asm volatile("ldmatrix.sync.aligned.m8n8.x2.shared.b16 {%0,%1}, [%2];"
                 : "=r"(r[0]), "=r"(r[1]) : "r"(a));
}
static __device__ __forceinline__ void mma_f16(float* d, const uint32_t* a, const uint32_t* b) {
    asm volatile(
        "mma.sync.aligned.m16n8k16.row.col.f32.f16.f16.f32 "
        "{%0,%1,%2,%3}, {%4,%5,%6,%7}, {%8,%9}, {%0,%1,%2,%3};"
        : "+f"(d[0]), "+f"(d[1]), "+f"(d[2]), "+f"(d[3])
        : "r"(a[0]), "r"(a[1]), "r"(a[2]), "r"(a[3]), "r"(b[0]), "r"(b[1]));
}

__global__ __launch_bounds__(256, 2)
void ensemble_lenet_mma(const float* __restrict__ params,
                        const float* __restrict__ batch,
                        float* __restrict__ out)
{
    extern __shared__ __align__(16) char smem[];
    half*  AH   = (half*)(smem + O_AH);
    half*  BH   = (half*)(smem + O_BH);
    half*  BL   = (half*)(smem + O_BL);
    float* sa2  = (float*)(smem + O_SA2);
    float* sw1  = (float*)(smem + O_SW1);
    float* sb1  = (float*)(smem + O_SB1);
    float* sb2  = (float*)(smem + O_SB2);
    float* sdot = (float*)(smem + O_SDOT);
    const uint32_t sb  = smem_u32(smem);
    const uint32_t uAH = sb + O_AH;
    const uint32_t uBH = sb + O_BH;
    const uint32_t uBL = sb + O_BL;

    const int blk   = blockIdx.x;
    const int init  = blk >> 6;
    const int npair = blk & 63;
    const int t     = threadIdx.x;
    const int img   = t >> 7;
    const int tl    = t & 127;

    const float* __restrict__ P = params + init * TOTAL_P;

    // ---------- stage 2 images (into BH region, pre-B) + conv1 params ----------
    {
        float* simg = (float*)(smem + O_BH);
        const float* ib = batch + (npair * 2) * 784;
        for (int idx = t; idx < 1568; idx += 256) simg[idx] = ib[idx];
        for (int idx = t; idx < 400;  idx += 256) sw1[idx] = P[idx];
        if (t < 16) sb1[t] = P[OFF_B1 + t];
        if (t < 32) sb2[t] = P[OFF_B2 + t];
    }
    __syncthreads();

    // ---------- conv1 + relu + pool -> AH (single fp16 rn) ----------
    {
        const int co = (tl >> 3) & 15;
        const int l8 = tl & 7;
        float w1r[25];
        #pragma unroll
        for (int q = 0; q < 25; q++) w1r[q] = sw1[co * 25 + q];
        const float b1 = sb1[co];
        const float* imgp = (const float*)(smem + O_BH) + img * 784;

        #pragma unroll 2
        for (int k = 0; k < 18; k++) {
            const int idx = l8 + (k << 3);       // 0..143
            const int py = idx / 12;
            const int px = idx - py * 12;
            const int iy = py * 2, ix = px * 2;

            float a00 = b1, a01 = b1, a10 = b1, a11 = b1;
            #pragma unroll
            for (int r = 0; r < 6; r++) {
                const float2* rp = (const float2*)(imgp + (iy + r) * 28 + ix);
                const float2 v0 = rp[0], v1 = rp[1], v2 = rp[2];
                float row[6];
                row[0]=v0.x; row[1]=v0.y; row[2]=v1.x; row[3]=v1.y; row[4]=v2.x; row[5]=v2.y;
                if (r < 5) {
                    #pragma unroll
                    for (int dx = 0; dx < 5; dx++) {
                        const float w = w1r[r * 5 + dx];
                        a00 = fmaf(row[dx],     w, a00);
                        a01 = fmaf(row[dx + 1], w, a01);
                    }
                }
                if (r >= 1) {
                    #pragma unroll
                    for (int dx = 0; dx < 5; dx++) {
                        const float w = w1r[(r - 1) * 5 + dx];
                        a10 = fmaf(row[dx],     w, a10);
                        a11 = fmaf(row[dx + 1], w, a11);
                    }
                }
            }
            const float v = fmaxf(fmaxf(fmaxf(a00, a01), fmaxf(a10, a11)), 0.0f);
            AH[img * A_I + py * A_Y + px * A_X + co] = __float2half_rn(v);
        }
    }
    __syncthreads();

    // ---------- stage conv2 weights, hi/lo split: BH/BL[tap][c2][ci] ----------
    for (int e = t; e < 12800; e += 256) {
        const int c2  = e / 400;
        const int r   = e - c2 * 400;
        const int ci  = r / 25;
        const int tap = r - ci * 25;
        const float v = P[OFF_W2 + e];
        const half vh = __float2half_rn(v);
        const half vl = __float2half_rn(v - __half2float(vh));
        const int bi = (tap * 32 + c2) * 24 + ci;
        BH[bi] = vh;
        BL[bi] = vl;
    }
    __syncthreads();

    // ---------- conv2 via ldmatrix + mma.sync, 2-pass (B split) ----------
    const int lane = t & 31;
    const int w    = t >> 5;
    const int g    = lane >> 2;
    const int tq   = lane & 3;
    const int mb   = w & 3;
    const int nb   = w >> 2;
    const int imw  = mb >> 1;
    const int pyb0 = ((2 * mb) & 3) * 2;        // mt=0 ; mt=1 -> pyb0+2

    // lane-constant address parts (bytes)
    const uint32_t a_lane = uAH + 2u * (uint32_t)(imw * A_I + ((lane & 8) ? A_Y : 0)
                                                + (lane & 7) * A_X + ((lane & 16) ? 8 : 0));
    const uint32_t b_lane = 2u * (uint32_t)((nb * 16 + (lane & 7)) * 24 + ((lane & 8) ? 8 : 0));

    float acc[2][2][4];
    #pragma unroll
    for (int i = 0; i < 2; i++)
        #pragma unroll
        for (int jn = 0; jn < 2; jn++)
            #pragma unroll
            for (int q = 0; q < 4; q++) acc[i][jn][q] = 0.0f;

    #pragma unroll
    for (int dy = 0; dy < 5; dy++) {
        #pragma unroll
        for (int dx = 0; dx < 5; dx++) {
            const int tap = dy * 5 + dx;

            uint32_t ah0[4], ah1[4];
            ldsm_x4(ah0, a_lane + 2u * (uint32_t)((pyb0 + dy) * A_Y + dx * A_X));
            ldsm_x4(ah1, a_lane + 2u * (uint32_t)((pyb0 + 2 + dy) * A_Y + dx * A_X));

            uint32_t bh[2][2], bl[2][2];
            #pragma unroll
            for (int nt = 0; nt < 2; nt++) {
                const uint32_t bo = b_lane + 2u * (uint32_t)(tap * B_T + nt * 192);
                ldsm_x2(bh[nt], uBH + bo);
                ldsm_x2(bl[nt], uBL + bo);
            }
            #pragma unroll
            for (int nt = 0; nt < 2; nt++) {
                mma_f16(acc[0][nt], ah0, bh[nt]);
                mma_f16(acc[0][nt], ah0, bl[nt]);
                mma_f16(acc[1][nt], ah1, bh[nt]);
                mma_f16(acc[1][nt], ah1, bl[nt]);
            }
        }
    }

    // ---------- epilogue: relu + 2x2 pool + bias -> sa2[img][pos16*32 + c2] ----------
    #pragma unroll
    for (int mt = 0; mt < 2; mt++) {
        const int tau = 2 * mb + mt;
        const int ppy = tau & 3;
        #pragma unroll
        for (int nt = 0; nt < 2; nt++) {
            #pragma unroll
            for (int cp = 0; cp < 2; cp++) {
                float v = fmaxf(acc[mt][nt][cp], acc[mt][nt][cp + 2]);
                v = fmaxf(v, __shfl_xor_sync(0xFFFFFFFFu, v, 4));   // px pair (g, g^1)
                if ((g & 1) == 0) {
                    const int c2  = nb * 16 + nt * 8 + 2 * tq + cp;
                    const int ppx = g >> 1;
                    sa2[imw * 512 + (ppy * 4 + ppx) * 32 + c2] =
                        fmaxf(v + sb2[c2], 0.0f);
                }
            }
        }
    }
    __syncthreads();

    // ---------- dense 512 -> 10 (warp-uniform) ----------
    {
        const int o  = tl >> 3;
        const int oc = (o < 10) ? o : 9;
        const int l  = tl & 7;
        const float2* wr2 = (const float2*)(P + OFF_WD + oc * 512 + l * 64);
        const float* a2 = sa2 + img * 512;
        float partial = 0.0f;
        #pragma unroll
        for (int i2 = 0; i2 < 32; i2++) {
            const float2 wv = wr2[i2];
            const int f0 = l * 64 + i2 * 2;
            partial = fmaf(wv.x, a2[((f0    ) & 15) * 32 + ((f0    ) >> 4)], partial);
            partial = fmaf(wv.y, a2[((f0 + 1) & 15) * 32 + ((f0 + 1) >> 4)], partial);
        }
        #pragma unroll
        for (int off = 4; off; off >>= 1)
            partial += __shfl_down_sync(0xFFFFFFFFu, partial, off, 8);
        if (l == 0 && o < 10) sdot[img * 16 + o] = partial + P[OFF_BD + o];
    }
    __syncthreads();

    // ---------- log_softmax over 10, write out ----------
    if (t < 64) {
        const int im = t >> 5;
        const int lane2 = t & 31;
        const float v = (lane2 < 10) ? sdot[im * 16 + lane2] : -INFINITY;
        float mx = v;
        #pragma unroll
        for (int off = 16; off; off >>= 1)
            mx = fmaxf(mx, __shfl_xor_sync(0xFFFFFFFFu, mx, off));
        const float e = (lane2 < 10) ? __expf(v - mx) : 0.0f;
        float s = e;
        #pragma unroll
        for (int off = 16; off; off >>= 1)
            s += __shfl_xor_sync(0xFFFFFFFFu, s, off);
        if (lane2 < 10) {
            const int n = npair * 2 + im;
            out[(init * BATCH_N + n) * 10 + lane2] = v - mx - __logf(s);
        }
    }
}

extern "C" void kernel_launch(void* const* d_in, const int* in_sizes, int n_in,
                              void* d_out, int out_size)
{
    const float* params = (const float*)d_in[0];
    const float* batch  = (const float*)d_in[1];
    if (n_in >= 2 && in_sizes[0] != NUM_INITS * TOTAL_P) {
        params = (const float*)d_in[1];
        batch  = (const float*)d_in[0];
    }
    float* out = (float*)d_out;
    cudaFuncSetAttribute(ensemble_lenet_mma,
                         cudaFuncAttributeMaxDynamicSharedMemorySize, SMEM_BYTES);
    ensemble_lenet_mma<<<NUM_INITS * (BATCH_N / 2), 256, SMEM_BYTES>>>(params, batch, out);
}